// round 14
// baseline (speedup 1.0000x reference)
#include <cuda_runtime.h>
#include <cstdint>
#include <math.h>

#define T_ 4
#define B_ 32
#define L_ 196
#define D_ 384
#define H_ 1536
#define M_ (T_ * B_ * L_)            // 25088
#define BL_ (B_ * L_)                // 6272
#define SPLITS 196                   // one split per 128-row tile
#define NW 48                        // mask words per row (1536/32)

// ---------------------------------------------------------------------------
// Scratch (device globals; no allocations allowed)
// ---------------------------------------------------------------------------
__device__ __align__(256) float    g_y1[(size_t)M_ * H_];   // 154 MB
__device__ __align__(256) float    g_y2[(size_t)M_ * D_];   // 38.5 MB
__device__ __align__(256) uint32_t g_mask[(size_t)M_ * NW]; // 4.8 MB spike bitmask
__device__ double g_psum[SPLITS * H_];
__device__ double g_psq [SPLITS * H_];
__device__ float  g_mean1[H_], g_rstd1[H_];
__device__ float  g_mean2[D_], g_rstd2[D_];

__global__ void nop_k() {}   // profile-slot alignment (capture = 4th launch)

// ---------------------------------------------------------------------------
// fp32 FFMA2 SGEMM + fused BN-stat partials.
// A stored DUPLICATED in smem (As[k][2r]=As[k][2r+1]=a) so the inner loop
// loads (a,a) packs directly: per k-step 38 issues vs 52 (no broadcast MOVs).
// Same values, same pairing, same ascending-k chains → bit-identical to R12.
// ---------------------------------------------------------------------------
template <int N, int K>
__global__ __launch_bounds__(256)
void gemm_k(const float* __restrict__ Af, const float* __restrict__ Bp,
            const float* __restrict__ bias, float* __restrict__ C)
{
    constexpr int BM = 128, BN = 128, BK = 8;
    constexpr int KT = K / BK;
    __shared__ __align__(16) float As[2][BK][2 * BM];   // duplicated pairs, 16 KB
    __shared__ __align__(16) float Bs[2][BK][BN];       // 8 KB
    __shared__ float sSU[16][128];
    __shared__ float sSQ[16][128];

    const int tid = threadIdx.x;
    const int bx = blockIdx.x, by = blockIdx.y;
    const int tx = tid & 15, ty = tid >> 4;

    const int a_row = tid >> 1;
    const int a_k4  = (tid & 1) * 4;
    const int b_row = tid >> 5;
    const int b_c4  = (tid & 31) * 4;
    const unsigned aM = by * BM + a_row;

    float4 ra, rb;
    unsigned long long acc2[8][4];
#pragma unroll
    for (int i = 0; i < 8; i++)
#pragma unroll
        for (int j = 0; j < 4; j++) acc2[i][j] = 0ULL;

    auto g_load = [&](int kt) {
        ra = *(const float4*)(Af + (size_t)aM * K + kt * BK + a_k4);
        rb = *(const float4*)(Bp + (size_t)(kt * BK + b_row) * N + bx * BN + b_c4);
    };
    auto s_store = [&](int buf) {
        *(float2*)&As[buf][a_k4 + 0][2 * a_row] = make_float2(ra.x, ra.x);
        *(float2*)&As[buf][a_k4 + 1][2 * a_row] = make_float2(ra.y, ra.y);
        *(float2*)&As[buf][a_k4 + 2][2 * a_row] = make_float2(ra.z, ra.z);
        *(float2*)&As[buf][a_k4 + 3][2 * a_row] = make_float2(ra.w, ra.w);
        *(float4*)&Bs[buf][b_row][b_c4] = rb;
    };

    g_load(0);
    s_store(0);
    __syncthreads();

#pragma unroll 1
    for (int kt = 0; kt < KT; kt++) {
        const int cur = kt & 1;
        if (kt + 1 < KT) g_load(kt + 1);
#pragma unroll
        for (int k = 0; k < BK; k++) {
            // A broadcast pairs, pre-duplicated: (a_i, a_i)
            unsigned long long ad[8];
#pragma unroll
            for (int i = 0; i < 4; i++) {
                const ulonglong2 t =
                    *(const ulonglong2*)&As[cur][k][2 * (ty * 8) + 4 * i];
                ad[2 * i]     = t.x;
                ad[2 * i + 1] = t.y;
            }
            const ulonglong2 t0 = *(const ulonglong2*)&Bs[cur][k][tx * 8];
            const ulonglong2 t1 = *(const ulonglong2*)&Bs[cur][k][tx * 8 + 4];
            unsigned long long bd[4];
            bd[0] = t0.x; bd[1] = t0.y; bd[2] = t1.x; bd[3] = t1.y;
#pragma unroll
            for (int i = 0; i < 8; i++)
#pragma unroll
                for (int j = 0; j < 4; j++)
                    asm("fma.rn.f32x2 %0, %1, %2, %3;"
                        : "=l"(acc2[i][j])
                        : "l"(ad[i]), "l"(bd[j]), "l"(acc2[i][j]));
        }
        if (kt + 1 < KT) {
            s_store(cur ^ 1);
            __syncthreads();
        }
    }

    const int col = bx * BN + tx * 8;
    float bf[8];
    *(float4*)&bf[0] = *(const float4*)(bias + col);
    *(float4*)&bf[4] = *(const float4*)(bias + col + 4);

#pragma unroll
    for (int i = 0; i < 8; i++) {
        const size_t row = (size_t)(by * BM + ty * 8 + i);
        float o[8];
#pragma unroll
        for (int j = 0; j < 4; j++)
            asm("mov.b64 {%0, %1}, %2;"
                : "=f"(o[2 * j]), "=f"(o[2 * j + 1]) : "l"(acc2[i][j]));
        float4 v0, v1;
        v0.x = o[0] + bf[0]; v0.y = o[1] + bf[1];
        v0.z = o[2] + bf[2]; v0.w = o[3] + bf[3];
        v1.x = o[4] + bf[4]; v1.y = o[5] + bf[5];
        v1.z = o[6] + bf[6]; v1.w = o[7] + bf[7];
        *(float4*)(C + row * N + col)     = v0;
        *(float4*)(C + row * N + col + 4) = v1;
    }

#pragma unroll
    for (int j = 0; j < 8; j++) {
        float su = 0.0f, sq = 0.0f;
#pragma unroll
        for (int i = 0; i < 8; i++) {
            float lo, hi;
            asm("mov.b64 {%0, %1}, %2;" : "=f"(lo), "=f"(hi) : "l"(acc2[i][j >> 1]));
            const float o = ((j & 1) ? hi : lo) + bf[j];
            su += o;
            sq = fmaf(o, o, sq);
        }
        sSU[ty][tx * 8 + j] = su;
        sSQ[ty][tx * 8 + j] = sq;
    }
    __syncthreads();
    if (tid < 128) {
        double s = 0.0, q = 0.0;
#pragma unroll
        for (int u = 0; u < 16; u++) {
            s += (double)sSU[u][tid];
            q += (double)sSQ[u][tid];
        }
        g_psum[(size_t)by * N + bx * BN + tid] = s;
        g_psq [(size_t)by * N + bx * BN + tid] = q;
    }
}

// ---------------------------------------------------------------------------
// Sparse GEMM2 + fused stat partials (R12 verbatim — 190 us, bit-exact).
// KTP=192 (96KB smem, stats aliased onto weight tile) → 2 CTAs/SM.
// ---------------------------------------------------------------------------
#define RPB 128
#define CT  128
#define KTP 192

__global__ __launch_bounds__(512, 2)
void gemm2_sparse_k(const uint32_t* __restrict__ mask,
                    const float* __restrict__ W2,
                    const float* __restrict__ b2,
                    float* __restrict__ Y2)
{
    extern __shared__ float sW[];
    const int tid = threadIdx.x;
    const int lane = tid & 31, w = tid >> 5;
    const int ct = blockIdx.x;
    const int row0 = blockIdx.y * RPB + w * 8;
    const int c0 = ct * CT + lane * 4;

    unsigned long long aA[8], aB[8];
#pragma unroll
    for (int r = 0; r < 8; r++) { aA[r] = 0ULL; aB[r] = 0ULL; }

#pragma unroll 1
    for (int kt = 0; kt < 8; kt++) {
        __syncthreads();
        for (int i = tid; i < KTP * (CT / 4); i += 512) {
            const int k = i / (CT / 4), cc = (i % (CT / 4)) * 4;
            *(float4*)&sW[k * CT + cc] =
                *(const float4*)&W2[(size_t)(kt * KTP + k) * D_ + ct * CT + cc];
        }
        __syncthreads();

#pragma unroll
        for (int r = 0; r < 8; r++) {
            const uint32_t* mrow = mask + (size_t)(row0 + r) * NW + kt * 6;
            unsigned long long a0 = aA[r], a1 = aB[r];
#pragma unroll 1
            for (int wd = 0; wd < 6; wd++) {
                uint32_t m = mrow[wd];
                const float* base = sW + wd * 32 * CT + lane * 4;
                while (m) {
                    const int b = __ffs(m) - 1;
                    m &= m - 1;
                    const ulonglong2 v = *(const ulonglong2*)(base + b * CT);
                    asm("add.rn.f32x2 %0, %1, %2;" : "=l"(a0) : "l"(a0), "l"(v.x));
                    asm("add.rn.f32x2 %0, %1, %2;" : "=l"(a1) : "l"(a1), "l"(v.y));
                }
            }
            aA[r] = a0; aB[r] = a1;
        }
    }

    const float4 bv = *(const float4*)&b2[c0];
    float4 su = make_float4(0.f, 0.f, 0.f, 0.f);
    float4 sq = make_float4(0.f, 0.f, 0.f, 0.f);
#pragma unroll
    for (int r = 0; r < 8; r++) {
        float x0, x1, x2, x3;
        asm("mov.b64 {%0, %1}, %2;" : "=f"(x0), "=f"(x1) : "l"(aA[r]));
        asm("mov.b64 {%0, %1}, %2;" : "=f"(x2), "=f"(x3) : "l"(aB[r]));
        float4 o;
        o.x = x0 + bv.x; o.y = x1 + bv.y;
        o.z = x2 + bv.z; o.w = x3 + bv.w;
        *(float4*)&Y2[(size_t)(row0 + r) * D_ + c0] = o;
        su.x += o.x; sq.x = fmaf(o.x, o.x, sq.x);
        su.y += o.y; sq.y = fmaf(o.y, o.y, sq.y);
        su.z += o.z; sq.z = fmaf(o.z, o.z, sq.z);
        su.w += o.w; sq.w = fmaf(o.w, o.w, sq.w);
    }
    __syncthreads();
    float* sS = sW;   // weight tile dead after last pass
    *(float4*)&sS[w * 128 + lane * 4]        = su;
    *(float4*)&sS[2048 + w * 128 + lane * 4] = sq;
    __syncthreads();
    if (tid < 128) {
        double s = 0.0, q = 0.0;
#pragma unroll
        for (int u = 0; u < 16; u++) {
            s += (double)sS[u * 128 + tid];
            q += (double)sS[2048 + u * 128 + tid];
        }
        g_psum[(size_t)blockIdx.y * D_ + ct * CT + tid] = s;
        g_psq [(size_t)blockIdx.y * D_ + ct * CT + tid] = q;
    }
}

// ---------------------------------------------------------------------------
// Final stats: fp64 sum over 196 splits (ascending, deterministic)
// ---------------------------------------------------------------------------
template <int N>
__global__ void stats_final_k(float* __restrict__ meanf, float* __restrict__ rstdf)
{
    const int c = blockIdx.x * 256 + threadIdx.x;
    if (c >= N) return;
    double su = 0.0, sq = 0.0;
#pragma unroll 4
    for (int s = 0; s < SPLITS; s++) { su += g_psum[s * N + c]; sq += g_psq[s * N + c]; }
    const double mean = su / (double)M_;
    const double var  = sq / (double)M_ - mean * mean;
    meanf[c] = (float)mean;
    rstdf[c] = (float)(1.0 / sqrt((double)__fadd_rn((float)var, 1e-5f)));
}

// ---------------------------------------------------------------------------
// Layer-1 BN + LIF → spike bitmask via ballot
// ---------------------------------------------------------------------------
__global__ __launch_bounds__(256)
void lif1_k(const float* __restrict__ Y,
            const float* __restrict__ meanf, const float* __restrict__ rstdf,
            const float* __restrict__ gamma, const float* __restrict__ beta,
            uint32_t* __restrict__ mask)
{
    const int STR = BL_ * H_;
    const int idx = blockIdx.x * 256 + threadIdx.x;
    const int lane = threadIdx.x & 31;
    const int c = idx % H_;
    const int bl = idx / H_;
    const float mu = meanf[c], rs = rstdf[c], ga = gamma[c], be = beta[c];

    float v = 0.0f;
#pragma unroll
    for (int t = 0; t < T_; t++) {
        float y = Y[(size_t)idx + (size_t)t * STR];
        y = __fadd_rn(__fmul_rn(__fmul_rn(__fsub_rn(y, mu), rs), ga), be);
        v = __fadd_rn(v, __fmul_rn(__fsub_rn(y, v), 0.5f));
        const bool s = (v >= 1.0f);
        const uint32_t bm = __ballot_sync(0xFFFFFFFFu, s);
        if (lane == 0)
            mask[(size_t)(t * BL_ + bl) * NW + (c >> 5)] = bm;
        v = s ? 0.0f : v;
    }
}

// ---------------------------------------------------------------------------
// Layer-2 BN + LIF → fp32 spikes to d_out
// ---------------------------------------------------------------------------
__global__ __launch_bounds__(256)
void lif2_k(const float* __restrict__ Y,
            const float* __restrict__ meanf, const float* __restrict__ rstdf,
            const float* __restrict__ gamma, const float* __restrict__ beta,
            float* __restrict__ outp)
{
    const int STR = BL_ * D_;
    const int idx = blockIdx.x * 256 + threadIdx.x;
    if (idx >= STR) return;
    const int c = idx % D_;
    const float mu = meanf[c], rs = rstdf[c], ga = gamma[c], be = beta[c];

    float v = 0.0f;
#pragma unroll
    for (int t = 0; t < T_; t++) {
        float y = Y[(size_t)idx + (size_t)t * STR];
        y = __fadd_rn(__fmul_rn(__fmul_rn(__fsub_rn(y, mu), rs), ga), be);
        v = __fadd_rn(v, __fmul_rn(__fsub_rn(y, v), 0.5f));
        const bool s = (v >= 1.0f);
        outp[(size_t)idx + (size_t)t * STR] = s ? 1.0f : 0.0f;
        v = s ? 0.0f : v;
    }
}

// ---------------------------------------------------------------------------
// Launch (3 nops → capture slot lands on gemm_k)
// ---------------------------------------------------------------------------
extern "C" void kernel_launch(void* const* d_in, const int* in_sizes, int n_in,
                              void* d_out, int out_size)
{
    const float* x      = (const float*)d_in[0];
    const float* W1     = (const float*)d_in[1];
    const float* b1     = (const float*)d_in[2];
    const float* gamma1 = (const float*)d_in[3];
    const float* beta1  = (const float*)d_in[4];
    const float* W2     = (const float*)d_in[5];
    const float* b2     = (const float*)d_in[6];
    const float* gamma2 = (const float*)d_in[7];
    const float* beta2  = (const float*)d_in[8];

    void *y1, *y2, *mk, *m1, *r1, *m2, *r2;
    cudaGetSymbolAddress(&y1, g_y1);
    cudaGetSymbolAddress(&y2, g_y2);
    cudaGetSymbolAddress(&mk, g_mask);
    cudaGetSymbolAddress(&m1, g_mean1);
    cudaGetSymbolAddress(&r1, g_rstd1);
    cudaGetSymbolAddress(&m2, g_mean2);
    cudaGetSymbolAddress(&r2, g_rstd2);

    const int SMEM2 = KTP * CT * (int)sizeof(float);   // 98304 B → 2 CTAs/SM
    cudaFuncSetAttribute(gemm2_sparse_k,
                         cudaFuncAttributeMaxDynamicSharedMemorySize, SMEM2);

    nop_k<<<1, 1>>>();
    nop_k<<<1, 1>>>();
    nop_k<<<1, 1>>>();

    // Layer 1
    gemm_k<H_, D_><<<dim3(H_ / 128, M_ / 128), 256>>>(x, W1, b1, (float*)y1);
    stats_final_k<H_><<<H_ / 256, 256>>>((float*)m1, (float*)r1);
    lif1_k<<<(BL_ * H_) / 256, 256>>>(
        (const float*)y1, (const float*)m1, (const float*)r1, gamma1, beta1,
        (uint32_t*)mk);

    // Layer 2
    gemm2_sparse_k<<<dim3(D_ / CT, M_ / RPB), 512, SMEM2>>>(
        (const uint32_t*)mk, W2, b2, (float*)y2);
    stats_final_k<D_><<<(D_ + 255) / 256, 256>>>((float*)m2, (float*)r2);
    lif2_k<<<(BL_ * D_) / 256, 256>>>(
        (const float*)y2, (const float*)m2, (const float*)r2, gamma2, beta2,
        (float*)d_out);
}

// round 15
// speedup vs baseline: 1.1506x; 1.1506x over previous
#include <cuda_runtime.h>
#include <cstdint>
#include <math.h>

#define T_ 4
#define B_ 32
#define L_ 196
#define D_ 384
#define H_ 1536
#define M_ (T_ * B_ * L_)            // 25088
#define BL_ (B_ * L_)                // 6272
#define SPLITS 196                   // one split per 128-row tile
#define NW 48                        // mask words per row (1536/32)

// ---------------------------------------------------------------------------
// Scratch (device globals; no allocations allowed)
// ---------------------------------------------------------------------------
__device__ __align__(256) float    g_y1[(size_t)M_ * H_];   // 154 MB
__device__ __align__(256) float    g_y2[(size_t)M_ * D_];   // 38.5 MB
__device__ __align__(256) uint32_t g_mask[(size_t)M_ * NW]; // 4.8 MB spike bitmask
__device__ double g_psum[SPLITS * H_];
__device__ double g_psq [SPLITS * H_];
__device__ float  g_mean1[H_], g_rstd1[H_];
__device__ float  g_mean2[D_], g_rstd2[D_];

__global__ void nop_k() {}   // profile-slot alignment (capture = 4th launch)

// ---------------------------------------------------------------------------
// fp32 FFMA2 SGEMM + fused BN-stat partials.
// 512 threads, 8 rows x 4 cols per thread, accumulators packed along ROWS:
// A pairs (a_2i, a_2i+1) are consecutive in As -> direct 64-bit LDS, no dup;
// only 4 B-broadcast MOVs per k-step. ~64 regs -> 2 CTAs/SM = 32 warps.
// Per-element rn-chains ascending-k -> BIT-IDENTICAL to R12.
// ---------------------------------------------------------------------------
template <int N, int K>
__global__ __launch_bounds__(512, 2)
void gemm_k(const float* __restrict__ Af, const float* __restrict__ Bp,
            const float* __restrict__ bias, float* __restrict__ C)
{
    constexpr int BM = 128, BN = 128, BK = 8;
    constexpr int KT = K / BK;
    __shared__ __align__(16) float As[2][BK][BM];   // 8 KB
    __shared__ __align__(16) float Bs[2][BK][BN];   // 8 KB
    __shared__ float sSU[16][128];
    __shared__ float sSQ[16][128];

    const int tid = threadIdx.x;
    const int bx = blockIdx.x, by = blockIdx.y;
    const int tx = tid & 31;          // col group: cols tx*4 .. +4
    const int ty = tid >> 5;          // row group: rows ty*8 .. +8 (uniform/warp)

    const int a_row = tid >> 2;             // 0..127
    const int a_k2  = (tid & 3) * 2;        // 0,2,4,6
    const int b_row = tid >> 6;             // 0..7
    const int b_c2  = (tid & 63) * 2;       // 0..126
    const unsigned aM = by * BM + a_row;

    float2 ra2, rb2;
    unsigned long long acc2[4][4];   // [row-pair i][col j] = (C[2i][j], C[2i+1][j])
#pragma unroll
    for (int i = 0; i < 4; i++)
#pragma unroll
        for (int j = 0; j < 4; j++) acc2[i][j] = 0ULL;

    auto g_load = [&](int kt) {
        ra2 = *(const float2*)(Af + (size_t)aM * K + kt * BK + a_k2);
        rb2 = *(const float2*)(Bp + (size_t)(kt * BK + b_row) * N + bx * BN + b_c2);
    };
    auto s_store = [&](int buf) {
        As[buf][a_k2 + 0][a_row] = ra2.x;
        As[buf][a_k2 + 1][a_row] = ra2.y;
        *(float2*)&Bs[buf][b_row][b_c2] = rb2;
    };

    g_load(0);
    s_store(0);
    __syncthreads();

#pragma unroll 1
    for (int kt = 0; kt < KT; kt++) {
        const int cur = kt & 1;
        if (kt + 1 < KT) g_load(kt + 1);
#pragma unroll
        for (int k = 0; k < BK; k++) {
            // A row-pairs, consecutive floats: (a_{2i}, a_{2i+1}) direct
            const ulonglong2 ta = *(const ulonglong2*)&As[cur][k][ty * 8];
            const ulonglong2 tb = *(const ulonglong2*)&As[cur][k][ty * 8 + 4];
            unsigned long long ad[4];
            ad[0] = ta.x; ad[1] = ta.y; ad[2] = tb.x; ad[3] = tb.y;
            // B scalars, duplicated into both halves
            const float4 b4 = *(const float4*)&Bs[cur][k][tx * 4];
            unsigned long long bd[4];
            asm("mov.b64 %0, {%1, %1};" : "=l"(bd[0]) : "f"(b4.x));
            asm("mov.b64 %0, {%1, %1};" : "=l"(bd[1]) : "f"(b4.y));
            asm("mov.b64 %0, {%1, %1};" : "=l"(bd[2]) : "f"(b4.z));
            asm("mov.b64 %0, {%1, %1};" : "=l"(bd[3]) : "f"(b4.w));
#pragma unroll
            for (int i = 0; i < 4; i++)
#pragma unroll
                for (int j = 0; j < 4; j++)
                    asm("fma.rn.f32x2 %0, %1, %2, %3;"
                        : "=l"(acc2[i][j])
                        : "l"(ad[i]), "l"(bd[j]), "l"(acc2[i][j]));
        }
        if (kt + 1 < KT) {
            s_store(cur ^ 1);
            __syncthreads();
        }
    }

    const int col = bx * BN + tx * 4;
    float bf[4];
    *(float4*)&bf[0] = *(const float4*)(bias + col);

    // store y: rows ty*8+2i (lo halves) and ty*8+2i+1 (hi halves)
#pragma unroll
    for (int i = 0; i < 4; i++) {
        float lo[4], hi[4];
#pragma unroll
        for (int j = 0; j < 4; j++)
            asm("mov.b64 {%0, %1}, %2;" : "=f"(lo[j]), "=f"(hi[j]) : "l"(acc2[i][j]));
        const size_t r0 = (size_t)(by * BM + ty * 8 + 2 * i);
        float4 v0, v1;
        v0.x = lo[0] + bf[0]; v0.y = lo[1] + bf[1];
        v0.z = lo[2] + bf[2]; v0.w = lo[3] + bf[3];
        v1.x = hi[0] + bf[0]; v1.y = hi[1] + bf[1];
        v1.z = hi[2] + bf[2]; v1.w = hi[3] + bf[3];
        *(float4*)(C + r0 * N + col)       = v0;
        *(float4*)(C + (r0 + 1) * N + col) = v1;
    }

    // fused stat partials: fp32 over the 8 rows in ascending order (R12 order)
#pragma unroll
    for (int j = 0; j < 4; j++) {
        float su = 0.0f, sq = 0.0f;
#pragma unroll
        for (int i = 0; i < 4; i++) {
            float lo, hi;
            asm("mov.b64 {%0, %1}, %2;" : "=f"(lo), "=f"(hi) : "l"(acc2[i][j]));
            const float o0 = lo + bf[j];
            su += o0;
            sq = fmaf(o0, o0, sq);
            const float o1 = hi + bf[j];
            su += o1;
            sq = fmaf(o1, o1, sq);
        }
        sSU[ty][tx * 4 + j] = su;
        sSQ[ty][tx * 4 + j] = sq;
    }
    __syncthreads();
    if (tid < 128) {
        double s = 0.0, q = 0.0;
#pragma unroll
        for (int u = 0; u < 16; u++) {
            s += (double)sSU[u][tid];
            q += (double)sSQ[u][tid];
        }
        g_psum[(size_t)by * N + bx * BN + tid] = s;
        g_psq [(size_t)by * N + bx * BN + tid] = q;
    }
}

// ---------------------------------------------------------------------------
// Sparse GEMM2 + fused stat partials (R12 verbatim — 190 us, bit-exact).
// ---------------------------------------------------------------------------
#define RPB 128
#define CT  128
#define KTP 192

__global__ __launch_bounds__(512, 2)
void gemm2_sparse_k(const uint32_t* __restrict__ mask,
                    const float* __restrict__ W2,
                    const float* __restrict__ b2,
                    float* __restrict__ Y2)
{
    extern __shared__ float sW[];
    const int tid = threadIdx.x;
    const int lane = tid & 31, w = tid >> 5;
    const int ct = blockIdx.x;
    const int row0 = blockIdx.y * RPB + w * 8;
    const int c0 = ct * CT + lane * 4;

    unsigned long long aA[8], aB[8];
#pragma unroll
    for (int r = 0; r < 8; r++) { aA[r] = 0ULL; aB[r] = 0ULL; }

#pragma unroll 1
    for (int kt = 0; kt < 8; kt++) {
        __syncthreads();
        for (int i = tid; i < KTP * (CT / 4); i += 512) {
            const int k = i / (CT / 4), cc = (i % (CT / 4)) * 4;
            *(float4*)&sW[k * CT + cc] =
                *(const float4*)&W2[(size_t)(kt * KTP + k) * D_ + ct * CT + cc];
        }
        __syncthreads();

#pragma unroll
        for (int r = 0; r < 8; r++) {
            const uint32_t* mrow = mask + (size_t)(row0 + r) * NW + kt * 6;
            unsigned long long a0 = aA[r], a1 = aB[r];
#pragma unroll 1
            for (int wd = 0; wd < 6; wd++) {
                uint32_t m = mrow[wd];
                const float* base = sW + wd * 32 * CT + lane * 4;
                while (m) {
                    const int b = __ffs(m) - 1;
                    m &= m - 1;
                    const ulonglong2 v = *(const ulonglong2*)(base + b * CT);
                    asm("add.rn.f32x2 %0, %1, %2;" : "=l"(a0) : "l"(a0), "l"(v.x));
                    asm("add.rn.f32x2 %0, %1, %2;" : "=l"(a1) : "l"(a1), "l"(v.y));
                }
            }
            aA[r] = a0; aB[r] = a1;
        }
    }

    const float4 bv = *(const float4*)&b2[c0];
    float4 su = make_float4(0.f, 0.f, 0.f, 0.f);
    float4 sq = make_float4(0.f, 0.f, 0.f, 0.f);
#pragma unroll
    for (int r = 0; r < 8; r++) {
        float x0, x1, x2, x3;
        asm("mov.b64 {%0, %1}, %2;" : "=f"(x0), "=f"(x1) : "l"(aA[r]));
        asm("mov.b64 {%0, %1}, %2;" : "=f"(x2), "=f"(x3) : "l"(aB[r]));
        float4 o;
        o.x = x0 + bv.x; o.y = x1 + bv.y;
        o.z = x2 + bv.z; o.w = x3 + bv.w;
        *(float4*)&Y2[(size_t)(row0 + r) * D_ + c0] = o;
        su.x += o.x; sq.x = fmaf(o.x, o.x, sq.x);
        su.y += o.y; sq.y = fmaf(o.y, o.y, sq.y);
        su.z += o.z; sq.z = fmaf(o.z, o.z, sq.z);
        su.w += o.w; sq.w = fmaf(o.w, o.w, sq.w);
    }
    __syncthreads();
    float* sS = sW;   // weight tile dead after last pass
    *(float4*)&sS[w * 128 + lane * 4]        = su;
    *(float4*)&sS[2048 + w * 128 + lane * 4] = sq;
    __syncthreads();
    if (tid < 128) {
        double s = 0.0, q = 0.0;
#pragma unroll
        for (int u = 0; u < 16; u++) {
            s += (double)sS[u * 128 + tid];
            q += (double)sS[2048 + u * 128 + tid];
        }
        g_psum[(size_t)blockIdx.y * D_ + ct * CT + tid] = s;
        g_psq [(size_t)blockIdx.y * D_ + ct * CT + tid] = q;
    }
}

// ---------------------------------------------------------------------------
// Final stats: fp64 sum over 196 splits (ascending, deterministic)
// ---------------------------------------------------------------------------
template <int N>
__global__ void stats_final_k(float* __restrict__ meanf, float* __restrict__ rstdf)
{
    const int c = blockIdx.x * 256 + threadIdx.x;
    if (c >= N) return;
    double su = 0.0, sq = 0.0;
#pragma unroll 4
    for (int s = 0; s < SPLITS; s++) { su += g_psum[s * N + c]; sq += g_psq[s * N + c]; }
    const double mean = su / (double)M_;
    const double var  = sq / (double)M_ - mean * mean;
    meanf[c] = (float)mean;
    rstdf[c] = (float)(1.0 / sqrt((double)__fadd_rn((float)var, 1e-5f)));
}

// ---------------------------------------------------------------------------
// Layer-1 BN + LIF → spike bitmask via ballot
// ---------------------------------------------------------------------------
__global__ __launch_bounds__(256)
void lif1_k(const float* __restrict__ Y,
            const float* __restrict__ meanf, const float* __restrict__ rstdf,
            const float* __restrict__ gamma, const float* __restrict__ beta,
            uint32_t* __restrict__ mask)
{
    const int STR = BL_ * H_;
    const int idx = blockIdx.x * 256 + threadIdx.x;
    const int lane = threadIdx.x & 31;
    const int c = idx % H_;
    const int bl = idx / H_;
    const float mu = meanf[c], rs = rstdf[c], ga = gamma[c], be = beta[c];

    float v = 0.0f;
#pragma unroll
    for (int t = 0; t < T_; t++) {
        float y = Y[(size_t)idx + (size_t)t * STR];
        y = __fadd_rn(__fmul_rn(__fmul_rn(__fsub_rn(y, mu), rs), ga), be);
        v = __fadd_rn(v, __fmul_rn(__fsub_rn(y, v), 0.5f));
        const bool s = (v >= 1.0f);
        const uint32_t bm = __ballot_sync(0xFFFFFFFFu, s);
        if (lane == 0)
            mask[(size_t)(t * BL_ + bl) * NW + (c >> 5)] = bm;
        v = s ? 0.0f : v;
    }
}

// ---------------------------------------------------------------------------
// Layer-2 BN + LIF → fp32 spikes to d_out
// ---------------------------------------------------------------------------
__global__ __launch_bounds__(256)
void lif2_k(const float* __restrict__ Y,
            const float* __restrict__ meanf, const float* __restrict__ rstdf,
            const float* __restrict__ gamma, const float* __restrict__ beta,
            float* __restrict__ outp)
{
    const int STR = BL_ * D_;
    const int idx = blockIdx.x * 256 + threadIdx.x;
    if (idx >= STR) return;
    const int c = idx % D_;
    const float mu = meanf[c], rs = rstdf[c], ga = gamma[c], be = beta[c];

    float v = 0.0f;
#pragma unroll
    for (int t = 0; t < T_; t++) {
        float y = Y[(size_t)idx + (size_t)t * STR];
        y = __fadd_rn(__fmul_rn(__fmul_rn(__fsub_rn(y, mu), rs), ga), be);
        v = __fadd_rn(v, __fmul_rn(__fsub_rn(y, v), 0.5f));
        const bool s = (v >= 1.0f);
        outp[(size_t)idx + (size_t)t * STR] = s ? 1.0f : 0.0f;
        v = s ? 0.0f : v;
    }
}

// ---------------------------------------------------------------------------
// Launch (3 nops → capture slot lands on gemm_k)
// ---------------------------------------------------------------------------
extern "C" void kernel_launch(void* const* d_in, const int* in_sizes, int n_in,
                              void* d_out, int out_size)
{
    const float* x      = (const float*)d_in[0];
    const float* W1     = (const float*)d_in[1];
    const float* b1     = (const float*)d_in[2];
    const float* gamma1 = (const float*)d_in[3];
    const float* beta1  = (const float*)d_in[4];
    const float* W2     = (const float*)d_in[5];
    const float* b2     = (const float*)d_in[6];
    const float* gamma2 = (const float*)d_in[7];
    const float* beta2  = (const float*)d_in[8];

    void *y1, *y2, *mk, *m1, *r1, *m2, *r2;
    cudaGetSymbolAddress(&y1, g_y1);
    cudaGetSymbolAddress(&y2, g_y2);
    cudaGetSymbolAddress(&mk, g_mask);
    cudaGetSymbolAddress(&m1, g_mean1);
    cudaGetSymbolAddress(&r1, g_rstd1);
    cudaGetSymbolAddress(&m2, g_mean2);
    cudaGetSymbolAddress(&r2, g_rstd2);

    const int SMEM2 = KTP * CT * (int)sizeof(float);   // 98304 B → 2 CTAs/SM
    cudaFuncSetAttribute(gemm2_sparse_k,
                         cudaFuncAttributeMaxDynamicSharedMemorySize, SMEM2);

    nop_k<<<1, 1>>>();
    nop_k<<<1, 1>>>();
    nop_k<<<1, 1>>>();

    // Layer 1
    gemm_k<H_, D_><<<dim3(H_ / 128, M_ / 128), 512>>>(x, W1, b1, (float*)y1);
    stats_final_k<H_><<<H_ / 256, 256>>>((float*)m1, (float*)r1);
    lif1_k<<<(BL_ * H_) / 256, 256>>>(
        (const float*)y1, (const float*)m1, (const float*)r1, gamma1, beta1,
        (uint32_t*)mk);

    // Layer 2
    gemm2_sparse_k<<<dim3(D_ / CT, M_ / RPB), 512, SMEM2>>>(
        (const uint32_t*)mk, W2, b2, (float*)y2);
    stats_final_k<D_><<<(D_ + 255) / 256, 256>>>((float*)m2, (float*)r2);
    lif2_k<<<(BL_ * D_) / 256, 256>>>(
        (const float*)y2, (const float*)m2, (const float*)r2, gamma2, beta2,
        (float*)d_out);
}